// round 16
// baseline (speedup 1.0000x reference)
#include <cuda_runtime.h>
#include <cuda_fp16.h>
#include <math.h>

#define NN 50000
#define EE 800000
#define NBLK_SCAN 196            // ceil(50000/256)

typedef unsigned long long u64;

// ---------------- f32x2 packed-FMA helpers (bit-identical fp32) ----------------
__device__ __forceinline__ u64 pack2(float lo, float hi) {
    u64 r; asm("mov.b64 %0, {%1, %2};" : "=l"(r) : "f"(lo), "f"(hi)); return r;
}
__device__ __forceinline__ void ffma2(u64& d, u64 a, u64 b) {
    asm("fma.rn.f32x2 %0, %1, %2, %0;" : "+l"(d) : "l"(a), "l"(b));
}
__device__ __forceinline__ float2 unpack2(u64 v) {
    float2 f; asm("mov.b64 {%0, %1}, %2;" : "=f"(f.x), "=f"(f.y) : "l"(v)); return f;
}

// 8 halves (uint4) -> 8 floats
__device__ __forceinline__ void h8_to_f8(uint4 v, float* f) {
    const __half2* h = (const __half2*)&v;
    #pragma unroll
    for (int i = 0; i < 4; ++i) {
        float2 t = __half22float2(h[i]);
        f[2 * i] = t.x; f[2 * i + 1] = t.y;
    }
}
// 8 floats -> 8 halves (uint4)
__device__ __forceinline__ uint4 f8_to_h8(const float* f) {
    uint4 v;
    __half2* h = (__half2*)&v;
    #pragma unroll
    for (int i = 0; i < 4; ++i)
        h[i] = __float22half2_rn(make_float2(f[2 * i], f[2 * i + 1]));
    return v;
}

// ---------------- scratch (device globals, no runtime alloc) ----------------
__device__ int    g_deg[NN];               // zero-init; re-zeroed by fill2 each pass
__device__ int    g_off[NN + 1];
__device__ float  g_dinv[NN];
__device__ int    g_part[NBLK_SCAN];
__device__ int    g_rank[EE];              // edge rank within its target node
__device__ int2   g_edge[EE];              // {src, __float_as_int(ew)}
__device__ float  g_s[NN];                 // s[n] = sum of ew into n

__device__ __half g_A16[(size_t)NN * 64];  // conv1 init (fp16), ld 64
__device__ float  g_Ar [(size_t)NN * 64];  // conv1 root + b1 (fp32), ld 64
__device__ __half g_B16[(size_t)NN * 64];  // conv1 after t=0 (fp16), ld 64
__device__ __half g_H16[(size_t)NN * 128]; // [H(0:32)|PH(32:64)|PPH(64:96)|pad], fp16

__device__ float g_Wp1[128 * 128];         // packed [w1_init | w1_root]
__device__ float g_W3 [96 * 40];           // folded conv2 weights [WR; Wb; Wa]
__device__ float g_bG [40];                // constant-through-A bias
__device__ float g_bR [40];                // direct bias

// ---------------- initW: pack Wp1 + fold conv2 weights (side stream) ----------------
__global__ void initW_kernel(const float* __restrict__ w1i, const float* __restrict__ w1r,
                             const float* __restrict__ w2i, const float* __restrict__ w2d,
                             const float* __restrict__ w2r, const float* __restrict__ b2) {
    int i = blockIdx.x * blockDim.x + threadIdx.x;
    if (i < 16384) {                       // Wp1 : 128 x 128 = [w1_init | w1_root]
        int f = i >> 7, j = i & 127;
        float v;
        if (j < 64) { int k = j >> 5, h = j & 31; v = w1i[(k * 128 + f) * 32 + h]; }
        else        { int j2 = j - 64; int k = j2 >> 5, h = j2 & 31; v = w1r[(k * 128 + f) * 32 + h]; }
        g_Wp1[i] = v;
    } else if (i < 16384 + 96 * 40) {      // W3' : 96 x 40
        int i2 = i - 16384;
        int f = i2 / 40, g = i2 % 40;
        float v = 0.0f;
        if (f < 32) {
            v = 0.5f * (w2r[f * 40 + g] + w2r[(32 + f) * 40 + g]);
        } else if (f < 64) {
            int fr = f - 32;
            #pragma unroll
            for (int k = 0; k < 2; ++k) {
                float s = 0.0f;
                for (int j = 0; j < 40; ++j)
                    s = fmaf(w2r[(k * 32 + fr) * 40 + j], w2d[(k * 40 + j) * 40 + g], s);
                v += s;
            }
            v *= 0.5f;
        } else {
            int fr = f - 64;
            #pragma unroll
            for (int k = 0; k < 2; ++k) {
                float s = 0.0f;
                for (int j = 0; j < 40; ++j)
                    s = fmaf(w2i[(k * 32 + fr) * 40 + j], w2d[(k * 40 + j) * 40 + g], s);
                v += s;
            }
            v *= 0.5f;
        }
        g_W3[i2] = v;
    } else if (i < 16384 + 96 * 40 + 80) {
        int g = i - (16384 + 96 * 40);
        if (g < 40) {
            float v = 0.0f;
            #pragma unroll
            for (int k = 0; k < 2; ++k)
                for (int j = 0; j < 40; ++j)
                    v = fmaf(b2[k * 40 + j], w2d[(k * 40 + j) * 40 + g], v);
            g_bG[g] = 0.5f * v;
        } else {
            int gg = g - 40;
            g_bR[gg] = 0.5f * (b2[gg] + b2[40 + gg]);
        }
    }
}

// ---------------- rank: histogram + capture per-edge rank (8 edges/thread) ------
__global__ void rank_kernel(const int* __restrict__ col) {
    int i = (blockIdx.x * blockDim.x + threadIdx.x) * 8;
    if (i + 8 <= EE) {
        int4 c0 = *(const int4*)&col[i];
        int4 c1 = *(const int4*)&col[i + 4];
        int4 k0, k1;
        k0.x = atomicAdd(&g_deg[c0.x], 1);
        k0.y = atomicAdd(&g_deg[c0.y], 1);
        k0.z = atomicAdd(&g_deg[c0.z], 1);
        k0.w = atomicAdd(&g_deg[c0.w], 1);
        k1.x = atomicAdd(&g_deg[c1.x], 1);
        k1.y = atomicAdd(&g_deg[c1.y], 1);
        k1.z = atomicAdd(&g_deg[c1.z], 1);
        k1.w = atomicAdd(&g_deg[c1.w], 1);
        *(int4*)&g_rank[i]     = k0;
        *(int4*)&g_rank[i + 4] = k1;
    } else {
        for (; i < EE; ++i) g_rank[i] = atomicAdd(&g_deg[col[i]], 1);
    }
}

// ---------------- scan phase A: block-reduce degrees + dinv ----------------
__global__ void scanA_kernel() {
    __shared__ int sm[256];
    const int tid = threadIdx.x;
    const int i = blockIdx.x * 256 + tid;
    int d = (i < NN) ? g_deg[i] : 0;
    if (i < NN) g_dinv[i] = (d > 0) ? rsqrtf((float)d) : 0.0f;
    sm[tid] = d;
    __syncthreads();
    #pragma unroll
    for (int off = 128; off > 0; off >>= 1) {
        if (tid < off) sm[tid] += sm[tid + off];
        __syncthreads();
    }
    if (tid == 0) g_part[blockIdx.x] = sm[0];
    if (blockIdx.x == 0 && tid == 0) g_off[NN] = EE;
}

// ---------------- scan phase C: base from partials + in-block scan ----------------
__global__ void scanC_kernel() {
    __shared__ int sm[256];
    const int tid = threadIdx.x;
    const int i = blockIdx.x * 256 + tid;

    int p = (tid < blockIdx.x) ? g_part[tid] : 0;
    sm[tid] = p;
    __syncthreads();
    #pragma unroll
    for (int off = 128; off > 0; off >>= 1) {
        if (tid < off) sm[tid] += sm[tid + off];
        __syncthreads();
    }
    int base = sm[0];
    __syncthreads();

    int d = (i < NN) ? g_deg[i] : 0;
    sm[tid] = d;
    __syncthreads();
    #pragma unroll
    for (int off = 1; off < 256; off <<= 1) {
        int t = (tid >= off) ? sm[tid - off] : 0;
        __syncthreads();
        sm[tid] += t;
        __syncthreads();
    }
    if (i < NN) g_off[i] = base + sm[tid] - d;   // exclusive prefix
}

// ---------------- fill2: streaming scatter (8 edges/thread) + deg reset -------
__global__ void fill2_kernel(const int* __restrict__ row, const int* __restrict__ col) {
    const int gid = blockIdx.x * blockDim.x + threadIdx.x;
    int i = gid * 8;
    if (i + 8 <= EE) {
        int4 r0 = *(const int4*)&row[i];
        int4 r1 = *(const int4*)&row[i + 4];
        int4 c0 = *(const int4*)&col[i];
        int4 c1 = *(const int4*)&col[i + 4];
        int4 k0 = *(const int4*)&g_rank[i];
        int4 k1 = *(const int4*)&g_rank[i + 4];
        g_edge[g_off[c0.x] + k0.x] = make_int2(r0.x, __float_as_int(g_dinv[r0.x] * g_dinv[c0.x]));
        g_edge[g_off[c0.y] + k0.y] = make_int2(r0.y, __float_as_int(g_dinv[r0.y] * g_dinv[c0.y]));
        g_edge[g_off[c0.z] + k0.z] = make_int2(r0.z, __float_as_int(g_dinv[r0.z] * g_dinv[c0.z]));
        g_edge[g_off[c0.w] + k0.w] = make_int2(r0.w, __float_as_int(g_dinv[r0.w] * g_dinv[c0.w]));
        g_edge[g_off[c1.x] + k1.x] = make_int2(r1.x, __float_as_int(g_dinv[r1.x] * g_dinv[c1.x]));
        g_edge[g_off[c1.y] + k1.y] = make_int2(r1.y, __float_as_int(g_dinv[r1.y] * g_dinv[c1.y]));
        g_edge[g_off[c1.z] + k1.z] = make_int2(r1.z, __float_as_int(g_dinv[r1.z] * g_dinv[c1.z]));
        g_edge[g_off[c1.w] + k1.w] = make_int2(r1.w, __float_as_int(g_dinv[r1.w] * g_dinv[c1.w]));
    } else {
        for (; i < EE; ++i) {
            int r0 = row[i], c0 = col[i];
            g_edge[g_off[c0] + g_rank[i]] =
                make_int2(r0, __float_as_int(g_dinv[r0] * g_dinv[c0]));
        }
    }
    // reset degree counters for the NEXT pass's rank (deg already consumed)
    if (gid < NN) g_deg[gid] = 0;
}

// ---------------- GEMM1: [init|root+b1] = X @ Wp1; init->fp16, root->fp32 ----------------
__global__ void __launch_bounds__(256)
gemm128_kernel(const float* __restrict__ X, const float* __restrict__ W,
               const float* __restrict__ bias64,
               __half* __restrict__ A16, float* __restrict__ Ar, int nrows) {
    __shared__ float xs[16][132];
    __shared__ float ws[16][128];

    const int tid = threadIdx.x;
    const int tx  = tid & 15;
    const int ty  = tid >> 4;
    const int n0  = blockIdx.x * 128;

    u64 acc[8][4] = {};

    for (int f0 = 0; f0 < 128; f0 += 16) {
        #pragma unroll
        for (int l = 0; l < 2; ++l) {
            int idx = tid + l * 256;
            int m = idx >> 2, fq = idx & 3;
            float4 v = make_float4(0.f, 0.f, 0.f, 0.f);
            if (n0 + m < nrows)
                v = *(const float4*)&X[(size_t)(n0 + m) * 128 + f0 + fq * 4];
            xs[fq * 4 + 0][m] = v.x;
            xs[fq * 4 + 1][m] = v.y;
            xs[fq * 4 + 2][m] = v.z;
            xs[fq * 4 + 3][m] = v.w;
        }
        #pragma unroll
        for (int l = 0; l < 2; ++l) {
            int idx = tid + l * 256;
            int f = idx >> 5, j4 = idx & 31;
            *(float4*)&ws[f][j4 * 4] = *(const float4*)&W[(size_t)(f0 + f) * 128 + j4 * 4];
        }
        __syncthreads();
        #pragma unroll
        for (int f = 0; f < 16; ++f) {
            float4 xa = *(const float4*)&xs[f][ty * 8];
            float4 xb = *(const float4*)&xs[f][ty * 8 + 4];
            const u64* wp = (const u64*)&ws[f][tx * 8];
            u64 w0 = wp[0], w1 = wp[1], w2 = wp[2], w3 = wp[3];
            u64 xr;
            xr = pack2(xa.x, xa.x);
            ffma2(acc[0][0], xr, w0); ffma2(acc[0][1], xr, w1);
            ffma2(acc[0][2], xr, w2); ffma2(acc[0][3], xr, w3);
            xr = pack2(xa.y, xa.y);
            ffma2(acc[1][0], xr, w0); ffma2(acc[1][1], xr, w1);
            ffma2(acc[1][2], xr, w2); ffma2(acc[1][3], xr, w3);
            xr = pack2(xa.z, xa.z);
            ffma2(acc[2][0], xr, w0); ffma2(acc[2][1], xr, w1);
            ffma2(acc[2][2], xr, w2); ffma2(acc[2][3], xr, w3);
            xr = pack2(xa.w, xa.w);
            ffma2(acc[3][0], xr, w0); ffma2(acc[3][1], xr, w1);
            ffma2(acc[3][2], xr, w2); ffma2(acc[3][3], xr, w3);
            xr = pack2(xb.x, xb.x);
            ffma2(acc[4][0], xr, w0); ffma2(acc[4][1], xr, w1);
            ffma2(acc[4][2], xr, w2); ffma2(acc[4][3], xr, w3);
            xr = pack2(xb.y, xb.y);
            ffma2(acc[5][0], xr, w0); ffma2(acc[5][1], xr, w1);
            ffma2(acc[5][2], xr, w2); ffma2(acc[5][3], xr, w3);
            xr = pack2(xb.z, xb.z);
            ffma2(acc[6][0], xr, w0); ffma2(acc[6][1], xr, w1);
            ffma2(acc[6][2], xr, w2); ffma2(acc[6][3], xr, w3);
            xr = pack2(xb.w, xb.w);
            ffma2(acc[7][0], xr, w0); ffma2(acc[7][1], xr, w1);
            ffma2(acc[7][2], xr, w2); ffma2(acc[7][3], xr, w3);
        }
        __syncthreads();
    }

    const int jb = tx * 8;
    #pragma unroll
    for (int r = 0; r < 8; ++r) {
        int n = n0 + ty * 8 + r;
        if (n >= nrows) continue;
        float2 p0 = unpack2(acc[r][0]);
        float2 p1 = unpack2(acc[r][1]);
        float2 p2 = unpack2(acc[r][2]);
        float2 p3 = unpack2(acc[r][3]);
        float y[8] = {p0.x, p0.y, p1.x, p1.y, p2.x, p2.y, p3.x, p3.y};
        if (jb < 64) {
            *(uint4*)&A16[(size_t)n * 64 + jb] = f8_to_h8(y);
        } else {
            int jr = jb - 64;
            #pragma unroll
            for (int c = 0; c < 8; ++c) y[c] += bias64[jr + c];
            *(float4*)&Ar[(size_t)n * 64 + jr]     = make_float4(y[0], y[1], y[2], y[3]);
            *(float4*)&Ar[(size_t)n * 64 + jr + 4] = make_float4(y[4], y[5], y[6], y[7]);
        }
    }
}

// ---------------- prop64h: width-64 fp16 gather, warp per node ----------------
template <bool DEEP>
__global__ void __launch_bounds__(256)
prop64h_kernel(const __half* __restrict__ src,     // fp16, ld 64
               const float* __restrict__ root,     // Ar, ld 64 (includes b1)
               const float* __restrict__ w1d,      // [2][32][32] (DEEP only)
               __half* __restrict__ outB,          // B16 (if !DEEP)
               __half* __restrict__ outH) {        // H16 (if DEEP), ld 128
    __shared__ float wd[2][32][32];
    __shared__ float smr[8][64];
    const int tid = threadIdx.x;
    if (DEEP) {
        #pragma unroll
        for (int l = 0; l < 8; ++l)
            ((float*)wd)[tid + l * 256] = w1d[tid + l * 256];
        __syncthreads();
    }

    const int gwarp = (blockIdx.x * blockDim.x + tid) >> 5;
    const int lane  = tid & 31;
    const int wwarp = tid >> 5;
    if (gwarp >= NN) return;
    const int n   = gwarp;
    const int beg = g_off[n];
    const int end = g_off[n + 1];
    const int eg = lane >> 3, cg = lane & 7;

    float acc[8] = {};
    int e = beg;
    for (; e + 8 <= end; e += 8) {
        int2 ea = g_edge[e + eg];
        int2 eb = g_edge[e + 4 + eg];
        uint4 va = ((const uint4*)(src + (size_t)ea.x * 64))[cg];
        uint4 vb = ((const uint4*)(src + (size_t)eb.x * 64))[cg];
        float fa[8], fb[8];
        h8_to_f8(va, fa);
        h8_to_f8(vb, fb);
        float wa = __int_as_float(ea.y), wb = __int_as_float(eb.y);
        #pragma unroll
        for (int j = 0; j < 8; ++j) {
            acc[j] = fmaf(wa, fa[j], acc[j]);
            acc[j] = fmaf(wb, fb[j], acc[j]);
        }
    }
    for (; e < end; e += 4) {
        int2 ea = (e + eg < end) ? g_edge[e + eg] : make_int2(0, 0);
        uint4 va = ((const uint4*)(src + (size_t)ea.x * 64))[cg];
        float fa[8];
        h8_to_f8(va, fa);
        float wa = __int_as_float(ea.y);
        #pragma unroll
        for (int j = 0; j < 8; ++j) acc[j] = fmaf(wa, fa[j], acc[j]);
    }
    #pragma unroll
    for (int j = 0; j < 8; ++j) {
        acc[j] += __shfl_xor_sync(0xffffffffu, acc[j], 8);
        acc[j] += __shfl_xor_sync(0xffffffffu, acc[j], 16);
    }

    if (!DEEP) {
        if (lane < 8) {
            const float4* rp = (const float4*)(root + (size_t)n * 64);
            float4 r0 = rp[cg * 2], r1 = rp[cg * 2 + 1];
            float y[8];
            y[0] = fmaxf(acc[0] + r0.x, 0.f); y[1] = fmaxf(acc[1] + r0.y, 0.f);
            y[2] = fmaxf(acc[2] + r0.z, 0.f); y[3] = fmaxf(acc[3] + r0.w, 0.f);
            y[4] = fmaxf(acc[4] + r1.x, 0.f); y[5] = fmaxf(acc[5] + r1.y, 0.f);
            y[6] = fmaxf(acc[6] + r1.z, 0.f); y[7] = fmaxf(acc[7] + r1.w, 0.f);
            *(uint4*)&outB[(size_t)n * 64 + cg * 8] = f8_to_h8(y);
        }
        return;
    }

    if (lane < 8) {
        #pragma unroll
        for (int j = 0; j < 8; ++j) smr[wwarp][cg * 8 + j] = acc[j];
    }
    __syncwarp();
    float a0 = smr[wwarp][lane];
    float a1 = smr[wwarp][lane + 32];

    float z0 = 0.f, z1 = 0.f;
    #pragma unroll
    for (int l = 0; l < 32; ++l) {
        float b0  = __shfl_sync(0xffffffffu, a0, l);
        float b1v = __shfl_sync(0xffffffffu, a1, l);
        z0 = fmaf(b0,  wd[0][l][lane], z0);
        z1 = fmaf(b1v, wd[1][l][lane], z1);
    }

    const float* rp = root + (size_t)n * 64;
    float y0 = fmaxf(z0 + rp[lane],      0.f);
    float y1 = fmaxf(z1 + rp[lane + 32], 0.f);
    outH[(size_t)n * 128 + lane] = __float2half_rn(0.5f * (y0 + y1));
}

// ---------------- prop32h: width-32 fp16 gather, warp per node ----------------
template <int SOFF, int DOFF, bool WITH_S>
__global__ void prop32h_kernel(__half* __restrict__ buf) {
    const int gwarp = (blockIdx.x * blockDim.x + threadIdx.x) >> 5;
    const int lane  = threadIdx.x & 31;
    if (gwarp >= NN) return;
    const int n   = gwarp;
    const int beg = g_off[n];
    const int end = g_off[n + 1];
    const int eg = lane >> 2, cg = lane & 3;
    const __half* src = buf + SOFF;

    float acc[8] = {};
    float sw = 0.f;
    int e = beg;
    for (; e + 16 <= end; e += 16) {
        int2 ea = g_edge[e + eg];
        int2 eb = g_edge[e + 8 + eg];
        uint4 va = ((const uint4*)(src + (size_t)ea.x * 128))[cg];
        uint4 vb = ((const uint4*)(src + (size_t)eb.x * 128))[cg];
        float fa[8], fb[8];
        h8_to_f8(va, fa);
        h8_to_f8(vb, fb);
        float wa = __int_as_float(ea.y), wb = __int_as_float(eb.y);
        #pragma unroll
        for (int j = 0; j < 8; ++j) {
            acc[j] = fmaf(wa, fa[j], acc[j]);
            acc[j] = fmaf(wb, fb[j], acc[j]);
        }
        if (WITH_S) sw += wa + wb;
    }
    for (; e < end; e += 8) {
        int2 ea = (e + eg < end) ? g_edge[e + eg] : make_int2(0, 0);
        uint4 va = ((const uint4*)(src + (size_t)ea.x * 128))[cg];
        float fa[8];
        h8_to_f8(va, fa);
        float wa = __int_as_float(ea.y);
        #pragma unroll
        for (int j = 0; j < 8; ++j) acc[j] = fmaf(wa, fa[j], acc[j]);
        if (WITH_S) sw += wa;
    }
    #pragma unroll
    for (int j = 0; j < 8; ++j) {
        acc[j] += __shfl_xor_sync(0xffffffffu, acc[j], 4);
        acc[j] += __shfl_xor_sync(0xffffffffu, acc[j], 8);
        acc[j] += __shfl_xor_sync(0xffffffffu, acc[j], 16);
    }
    if (WITH_S) {
        sw += __shfl_xor_sync(0xffffffffu, sw, 4);
        sw += __shfl_xor_sync(0xffffffffu, sw, 8);
        sw += __shfl_xor_sync(0xffffffffu, sw, 16);
    }
    if (lane < 4)
        *(uint4*)&buf[(size_t)n * 128 + DOFF + cg * 8] = f8_to_h8(acc);
    if (WITH_S && lane == 0) g_s[n] = sw;
}

// ---------------- gemm96 (fp16 X) + fused log_softmax ----------------
__global__ void __launch_bounds__(256)
gemm96lsm_kernel(const __half* __restrict__ X,      // H16, ld 128 (cols 0..95)
                 const float* __restrict__ W,       // 96 x 40
                 float* __restrict__ out, int nrows) {
    __shared__ float xs[16][132];
    __shared__ float ws[16][40];
    __shared__ float sbG[40], sbR[40];

    const int tid = threadIdx.x;
    const int tx  = tid & 7;
    const int ty  = tid >> 3;
    const int n0  = blockIdx.x * 128;

    if (tid < 40) { sbG[tid] = g_bG[tid]; sbR[tid] = g_bR[tid]; }

    float acc[4][5] = {};

    for (int f0 = 0; f0 < 96; f0 += 16) {
        {
            int m = tid >> 1, q = tid & 1;
            uint4 v = make_uint4(0, 0, 0, 0);
            if (n0 + m < nrows)
                v = *(const uint4*)&X[(size_t)(n0 + m) * 128 + f0 + q * 8];
            float fv[8];
            h8_to_f8(v, fv);
            #pragma unroll
            for (int j = 0; j < 8; ++j) xs[q * 8 + j][m] = fv[j];
        }
        #pragma unroll
        for (int l = 0; l < 3; ++l) {
            int idx = tid + l * 256;
            if (idx < 640) {
                int f = idx / 40, j = idx - f * 40;
                ws[f][j] = W[(size_t)(f0 + f) * 40 + j];
            }
        }
        __syncthreads();
        #pragma unroll
        for (int f = 0; f < 16; ++f) {
            float w[5];
            #pragma unroll
            for (int c = 0; c < 5; ++c) w[c] = ws[f][tx * 5 + c];
            #pragma unroll
            for (int r = 0; r < 4; ++r) {
                float xv = xs[f][ty * 4 + r];
                #pragma unroll
                for (int c = 0; c < 5; ++c) acc[r][c] = fmaf(xv, w[c], acc[r][c]);
            }
        }
        __syncthreads();
    }

    #pragma unroll
    for (int r = 0; r < 4; ++r) {
        int n = n0 + ty * 4 + r;
        float sv = (n < nrows) ? g_s[n] : 0.f;
        float y[5];
        #pragma unroll
        for (int c = 0; c < 5; ++c) {
            int j = tx * 5 + c;
            y[c] = acc[r][c] + sv * sbG[j] + sbR[j];
        }
        float m = y[0];
        #pragma unroll
        for (int c = 1; c < 5; ++c) m = fmaxf(m, y[c]);
        #pragma unroll
        for (int o = 1; o < 8; o <<= 1) m = fmaxf(m, __shfl_xor_sync(0xffffffffu, m, o));
        float s = 0.f;
        #pragma unroll
        for (int c = 0; c < 5; ++c) s += expf(y[c] - m);
        #pragma unroll
        for (int o = 1; o < 8; o <<= 1) s += __shfl_xor_sync(0xffffffffu, s, o);
        float lse = m + logf(s);
        if (n < nrows) {
            #pragma unroll
            for (int c = 0; c < 5; ++c)
                out[(size_t)n * 40 + tx * 5 + c] = y[c] - lse;
        }
    }
}

// ---------------- launch ----------------
extern "C" void kernel_launch(void* const* d_in, const int* in_sizes, int n_in,
                              void* d_out, int out_size) {
    const float* x    = (const float*)d_in[0];
    const int*   eidx = (const int*)  d_in[1];
    const float* w1i  = (const float*)d_in[2];
    const float* w1d  = (const float*)d_in[3];
    const float* w1r  = (const float*)d_in[4];
    const float* b1   = (const float*)d_in[5];
    const float* w2i  = (const float*)d_in[6];
    const float* w2d  = (const float*)d_in[7];
    const float* w2r  = (const float*)d_in[8];
    const float* b2   = (const float*)d_in[9];
    float* outp = (float*)d_out;

    const int* row = eidx;
    const int* col = eidx + EE;

    __half *A16, *B16, *H16;
    float *Ar, *Wp1, *W3;
    cudaGetSymbolAddress((void**)&A16, g_A16);
    cudaGetSymbolAddress((void**)&Ar,  g_Ar);
    cudaGetSymbolAddress((void**)&B16, g_B16);
    cudaGetSymbolAddress((void**)&H16, g_H16);
    cudaGetSymbolAddress((void**)&Wp1, g_Wp1);
    cudaGetSymbolAddress((void**)&W3,  g_W3);

    static cudaStream_t s2 = nullptr;
    static cudaEvent_t  evFork = nullptr, evJoin = nullptr;
    if (s2 == nullptr) {
        cudaStreamCreateWithFlags(&s2, cudaStreamNonBlocking);
        cudaEventCreateWithFlags(&evFork, cudaEventDisableTiming);
        cudaEventCreateWithFlags(&evJoin, cudaEventDisableTiming);
    }

    const int TB = 256;
    const int nblkE8 = (EE / 8 + TB - 1) / TB;         // 391
    const int nblkW  = (NN * 32 + TB - 1) / TB;        // 6250 (warp per node)
    const int gR = (NN + 127) / 128;                   // 391 row tiles

    // fork immediately: side stream does weight folding + gemm128
    cudaEventRecord(evFork, 0);
    cudaStreamWaitEvent(s2, evFork, 0);
    initW_kernel<<<(16384 + 96 * 40 + 80 + TB - 1) / TB, TB, 0, s2>>>(w1i, w1r, w2i, w2d, w2r, b2);
    gemm128_kernel<<<gR, TB, 0, s2>>>(x, Wp1, b1, A16, Ar, NN);
    cudaEventRecord(evJoin, s2);

    // main stream: graph prep (deg zeroed by previous pass's fill2 / static init)
    rank_kernel<<<nblkE8, TB>>>(col);
    scanA_kernel<<<NBLK_SCAN, 256>>>();
    scanC_kernel<<<NBLK_SCAN, 256>>>();
    fill2_kernel<<<nblkE8, TB>>>(row, col);

    cudaStreamWaitEvent(0, evJoin, 0);

    // ---- conv1 (fp16 gathers, fp32 math) ----
    prop64h_kernel<false><<<nblkW, TB>>>(A16, Ar, nullptr, B16, nullptr);
    prop64h_kernel<true ><<<nblkW, TB>>>(B16, Ar, w1d, nullptr, H16);  // H -> cols 0..31

    // ---- conv2 (fully folded, fp16 features) ----
    prop32h_kernel<0, 32, true ><<<nblkW, TB>>>(H16);        // PH  = A(H),  + s[n]
    prop32h_kernel<32, 64, false><<<nblkW, TB>>>(H16);       // PPH = A(PH)
    gemm96lsm_kernel<<<gR, TB>>>(H16, W3, outp, NN);
}

// round 17
// speedup vs baseline: 1.5643x; 1.5643x over previous
#include <cuda_runtime.h>
#include <cuda_fp16.h>
#include <math.h>

#define NN 50000
#define EE 800000
#define NBLK_SCAN 196            // ceil(50000/256)

typedef unsigned long long u64;

// ---------------- f32x2 packed-FMA helpers (bit-identical fp32) ----------------
__device__ __forceinline__ u64 pack2(float lo, float hi) {
    u64 r; asm("mov.b64 %0, {%1, %2};" : "=l"(r) : "f"(lo), "f"(hi)); return r;
}
__device__ __forceinline__ void ffma2(u64& d, u64 a, u64 b) {
    asm("fma.rn.f32x2 %0, %1, %2, %0;" : "+l"(d) : "l"(a), "l"(b));
}
__device__ __forceinline__ float2 unpack2(u64 v) {
    float2 f; asm("mov.b64 {%0, %1}, %2;" : "=f"(f.x), "=f"(f.y) : "l"(v)); return f;
}

// 8 halves (uint4) -> 8 floats
__device__ __forceinline__ void h8_to_f8(uint4 v, float* f) {
    const __half2* h = (const __half2*)&v;
    #pragma unroll
    for (int i = 0; i < 4; ++i) {
        float2 t = __half22float2(h[i]);
        f[2 * i] = t.x; f[2 * i + 1] = t.y;
    }
}
// 8 floats -> 8 halves (uint4)
__device__ __forceinline__ uint4 f8_to_h8(const float* f) {
    uint4 v;
    __half2* h = (__half2*)&v;
    #pragma unroll
    for (int i = 0; i < 4; ++i)
        h[i] = __float22half2_rn(make_float2(f[2 * i], f[2 * i + 1]));
    return v;
}

// ---------------- scratch (device globals, no runtime alloc) ----------------
__device__ int    g_deg[NN];
__device__ int    g_off[NN + 1];
__device__ float  g_dinv[NN];
__device__ int    g_part[NBLK_SCAN];
__device__ int    g_rank[EE];              // edge rank within its target node
__device__ int2   g_edge[EE];              // {src, __float_as_int(ew)}
__device__ float  g_s[NN];                 // s[n] = sum of ew into n

__device__ __half g_A16[(size_t)NN * 64];  // conv1 init (fp16), ld 64
__device__ float  g_Ar [(size_t)NN * 64];  // conv1 root + b1 (fp32), ld 64
__device__ __half g_B16[(size_t)NN * 64];  // conv1 after t=0 (fp16), ld 64
__device__ __half g_H16[(size_t)NN * 128]; // [H(0:32)|PH(32:64)|PPH(64:96)|pad], fp16

__device__ float g_Wp1[128 * 128];         // packed [w1_init | w1_root]
__device__ float g_W3 [96 * 40];           // folded conv2 weights [WR; Wb; Wa]
__device__ float g_bG [40];                // constant-through-A bias
__device__ float g_bR [40];                // direct bias

// ---------------- initD: zero degree (main stream, tiny) ----------------
__global__ void initD_kernel() {
    int i = blockIdx.x * blockDim.x + threadIdx.x;
    if (i < NN) g_deg[i] = 0;
}

// ---------------- initW: pack Wp1 + fold conv2 weights (side stream) ----------------
__global__ void initW_kernel(const float* __restrict__ w1i, const float* __restrict__ w1r,
                             const float* __restrict__ w2i, const float* __restrict__ w2d,
                             const float* __restrict__ w2r, const float* __restrict__ b2) {
    int i = blockIdx.x * blockDim.x + threadIdx.x;
    if (i < 16384) {                       // Wp1 : 128 x 128 = [w1_init | w1_root]
        int f = i >> 7, j = i & 127;
        float v;
        if (j < 64) { int k = j >> 5, h = j & 31; v = w1i[(k * 128 + f) * 32 + h]; }
        else        { int j2 = j - 64; int k = j2 >> 5, h = j2 & 31; v = w1r[(k * 128 + f) * 32 + h]; }
        g_Wp1[i] = v;
    } else if (i < 16384 + 96 * 40) {      // W3' : 96 x 40
        int i2 = i - 16384;
        int f = i2 / 40, g = i2 % 40;
        float v = 0.0f;
        if (f < 32) {
            v = 0.5f * (w2r[f * 40 + g] + w2r[(32 + f) * 40 + g]);
        } else if (f < 64) {
            int fr = f - 32;
            #pragma unroll
            for (int k = 0; k < 2; ++k) {
                float s = 0.0f;
                for (int j = 0; j < 40; ++j)
                    s = fmaf(w2r[(k * 32 + fr) * 40 + j], w2d[(k * 40 + j) * 40 + g], s);
                v += s;
            }
            v *= 0.5f;
        } else {
            int fr = f - 64;
            #pragma unroll
            for (int k = 0; k < 2; ++k) {
                float s = 0.0f;
                for (int j = 0; j < 40; ++j)
                    s = fmaf(w2i[(k * 32 + fr) * 40 + j], w2d[(k * 40 + j) * 40 + g], s);
                v += s;
            }
            v *= 0.5f;
        }
        g_W3[i2] = v;
    } else if (i < 16384 + 96 * 40 + 80) {
        int g = i - (16384 + 96 * 40);
        if (g < 40) {
            float v = 0.0f;
            #pragma unroll
            for (int k = 0; k < 2; ++k)
                for (int j = 0; j < 40; ++j)
                    v = fmaf(b2[k * 40 + j], w2d[(k * 40 + j) * 40 + g], v);
            g_bG[g] = 0.5f * v;
        } else {
            int gg = g - 40;
            g_bR[gg] = 0.5f * (b2[gg] + b2[40 + gg]);
        }
    }
}

// ---------------- rank: histogram + capture per-edge rank (4 edges/thread) ------
__global__ void rank_kernel(const int* __restrict__ col) {
    int i = (blockIdx.x * blockDim.x + threadIdx.x) * 4;
    if (i + 4 <= EE) {
        int4 c = *(const int4*)&col[i];
        int4 k;
        k.x = atomicAdd(&g_deg[c.x], 1);
        k.y = atomicAdd(&g_deg[c.y], 1);
        k.z = atomicAdd(&g_deg[c.z], 1);
        k.w = atomicAdd(&g_deg[c.w], 1);
        *(int4*)&g_rank[i] = k;
    } else {
        for (; i < EE; ++i) g_rank[i] = atomicAdd(&g_deg[col[i]], 1);
    }
}

// ---------------- scan phase A: block-reduce degrees + dinv ----------------
__global__ void scanA_kernel() {
    __shared__ int sm[256];
    const int tid = threadIdx.x;
    const int i = blockIdx.x * 256 + tid;
    int d = (i < NN) ? g_deg[i] : 0;
    if (i < NN) g_dinv[i] = (d > 0) ? rsqrtf((float)d) : 0.0f;
    sm[tid] = d;
    __syncthreads();
    #pragma unroll
    for (int off = 128; off > 0; off >>= 1) {
        if (tid < off) sm[tid] += sm[tid + off];
        __syncthreads();
    }
    if (tid == 0) g_part[blockIdx.x] = sm[0];
    if (blockIdx.x == 0 && tid == 0) g_off[NN] = EE;
}

// ---------------- scan phase C: base from partials + in-block scan ----------------
__global__ void scanC_kernel() {
    __shared__ int sm[256];
    const int tid = threadIdx.x;
    const int i = blockIdx.x * 256 + tid;

    int p = (tid < blockIdx.x) ? g_part[tid] : 0;
    sm[tid] = p;
    __syncthreads();
    #pragma unroll
    for (int off = 128; off > 0; off >>= 1) {
        if (tid < off) sm[tid] += sm[tid + off];
        __syncthreads();
    }
    int base = sm[0];
    __syncthreads();

    int d = (i < NN) ? g_deg[i] : 0;
    sm[tid] = d;
    __syncthreads();
    #pragma unroll
    for (int off = 1; off < 256; off <<= 1) {
        int t = (tid >= off) ? sm[tid - off] : 0;
        __syncthreads();
        sm[tid] += t;
        __syncthreads();
    }
    if (i < NN) g_off[i] = base + sm[tid] - d;   // exclusive prefix
}

// ---------------- fill2: streaming scatter (no atomics) ----------------
__global__ void fill2_kernel(const int* __restrict__ row, const int* __restrict__ col) {
    int i = (blockIdx.x * blockDim.x + threadIdx.x) * 4;
    if (i + 4 <= EE) {
        int4 r = *(const int4*)&row[i];
        int4 c = *(const int4*)&col[i];
        int4 k = *(const int4*)&g_rank[i];
        float w0 = g_dinv[r.x] * g_dinv[c.x];
        float w1 = g_dinv[r.y] * g_dinv[c.y];
        float w2 = g_dinv[r.z] * g_dinv[c.z];
        float w3 = g_dinv[r.w] * g_dinv[c.w];
        int p0 = g_off[c.x] + k.x;
        int p1 = g_off[c.y] + k.y;
        int p2 = g_off[c.z] + k.z;
        int p3 = g_off[c.w] + k.w;
        g_edge[p0] = make_int2(r.x, __float_as_int(w0));
        g_edge[p1] = make_int2(r.y, __float_as_int(w1));
        g_edge[p2] = make_int2(r.z, __float_as_int(w2));
        g_edge[p3] = make_int2(r.w, __float_as_int(w3));
    } else {
        for (; i < EE; ++i) {
            int r0 = row[i], c0 = col[i];
            int p0 = g_off[c0] + g_rank[i];
            g_edge[p0] = make_int2(r0, __float_as_int(g_dinv[r0] * g_dinv[c0]));
        }
    }
}

// ---------------- GEMM1: [init|root+b1] = X @ Wp1; init->fp16, root->fp32 ----------------
__global__ void __launch_bounds__(256)
gemm128_kernel(const float* __restrict__ X, const float* __restrict__ W,
               const float* __restrict__ bias64,
               __half* __restrict__ A16, float* __restrict__ Ar, int nrows) {
    __shared__ float xs[16][132];
    __shared__ float ws[16][128];

    const int tid = threadIdx.x;
    const int tx  = tid & 15;
    const int ty  = tid >> 4;
    const int n0  = blockIdx.x * 128;

    u64 acc[8][4] = {};

    for (int f0 = 0; f0 < 128; f0 += 16) {
        #pragma unroll
        for (int l = 0; l < 2; ++l) {
            int idx = tid + l * 256;
            int m = idx >> 2, fq = idx & 3;
            float4 v = make_float4(0.f, 0.f, 0.f, 0.f);
            if (n0 + m < nrows)
                v = *(const float4*)&X[(size_t)(n0 + m) * 128 + f0 + fq * 4];
            xs[fq * 4 + 0][m] = v.x;
            xs[fq * 4 + 1][m] = v.y;
            xs[fq * 4 + 2][m] = v.z;
            xs[fq * 4 + 3][m] = v.w;
        }
        #pragma unroll
        for (int l = 0; l < 2; ++l) {
            int idx = tid + l * 256;
            int f = idx >> 5, j4 = idx & 31;
            *(float4*)&ws[f][j4 * 4] = *(const float4*)&W[(size_t)(f0 + f) * 128 + j4 * 4];
        }
        __syncthreads();
        #pragma unroll
        for (int f = 0; f < 16; ++f) {
            float4 xa = *(const float4*)&xs[f][ty * 8];
            float4 xb = *(const float4*)&xs[f][ty * 8 + 4];
            const u64* wp = (const u64*)&ws[f][tx * 8];
            u64 w0 = wp[0], w1 = wp[1], w2 = wp[2], w3 = wp[3];
            u64 xr;
            xr = pack2(xa.x, xa.x);
            ffma2(acc[0][0], xr, w0); ffma2(acc[0][1], xr, w1);
            ffma2(acc[0][2], xr, w2); ffma2(acc[0][3], xr, w3);
            xr = pack2(xa.y, xa.y);
            ffma2(acc[1][0], xr, w0); ffma2(acc[1][1], xr, w1);
            ffma2(acc[1][2], xr, w2); ffma2(acc[1][3], xr, w3);
            xr = pack2(xa.z, xa.z);
            ffma2(acc[2][0], xr, w0); ffma2(acc[2][1], xr, w1);
            ffma2(acc[2][2], xr, w2); ffma2(acc[2][3], xr, w3);
            xr = pack2(xa.w, xa.w);
            ffma2(acc[3][0], xr, w0); ffma2(acc[3][1], xr, w1);
            ffma2(acc[3][2], xr, w2); ffma2(acc[3][3], xr, w3);
            xr = pack2(xb.x, xb.x);
            ffma2(acc[4][0], xr, w0); ffma2(acc[4][1], xr, w1);
            ffma2(acc[4][2], xr, w2); ffma2(acc[4][3], xr, w3);
            xr = pack2(xb.y, xb.y);
            ffma2(acc[5][0], xr, w0); ffma2(acc[5][1], xr, w1);
            ffma2(acc[5][2], xr, w2); ffma2(acc[5][3], xr, w3);
            xr = pack2(xb.z, xb.z);
            ffma2(acc[6][0], xr, w0); ffma2(acc[6][1], xr, w1);
            ffma2(acc[6][2], xr, w2); ffma2(acc[6][3], xr, w3);
            xr = pack2(xb.w, xb.w);
            ffma2(acc[7][0], xr, w0); ffma2(acc[7][1], xr, w1);
            ffma2(acc[7][2], xr, w2); ffma2(acc[7][3], xr, w3);
        }
        __syncthreads();
    }

    const int jb = tx * 8;
    #pragma unroll
    for (int r = 0; r < 8; ++r) {
        int n = n0 + ty * 8 + r;
        if (n >= nrows) continue;
        float2 p0 = unpack2(acc[r][0]);
        float2 p1 = unpack2(acc[r][1]);
        float2 p2 = unpack2(acc[r][2]);
        float2 p3 = unpack2(acc[r][3]);
        float y[8] = {p0.x, p0.y, p1.x, p1.y, p2.x, p2.y, p3.x, p3.y};
        if (jb < 64) {
            *(uint4*)&A16[(size_t)n * 64 + jb] = f8_to_h8(y);
        } else {
            int jr = jb - 64;
            #pragma unroll
            for (int c = 0; c < 8; ++c) y[c] += bias64[jr + c];
            *(float4*)&Ar[(size_t)n * 64 + jr]     = make_float4(y[0], y[1], y[2], y[3]);
            *(float4*)&Ar[(size_t)n * 64 + jr + 4] = make_float4(y[4], y[5], y[6], y[7]);
        }
    }
}

// ---------------- prop64h: width-64 fp16 gather, warp per node ----------------
template <bool DEEP>
__global__ void __launch_bounds__(256)
prop64h_kernel(const __half* __restrict__ src,     // fp16, ld 64
               const float* __restrict__ root,     // Ar, ld 64 (includes b1)
               const float* __restrict__ w1d,      // [2][32][32] (DEEP only)
               __half* __restrict__ outB,          // B16 (if !DEEP)
               __half* __restrict__ outH) {        // H16 (if DEEP), ld 128
    __shared__ float wd[2][32][32];
    __shared__ float smr[8][64];
    const int tid = threadIdx.x;
    if (DEEP) {
        #pragma unroll
        for (int l = 0; l < 8; ++l)
            ((float*)wd)[tid + l * 256] = w1d[tid + l * 256];
        __syncthreads();
    }

    const int gwarp = (blockIdx.x * blockDim.x + tid) >> 5;
    const int lane  = tid & 31;
    const int wwarp = tid >> 5;
    if (gwarp >= NN) return;
    const int n   = gwarp;
    const int beg = g_off[n];
    const int end = g_off[n + 1];
    const int eg = lane >> 3, cg = lane & 7;

    float acc[8] = {};
    int e = beg;
    for (; e + 8 <= end; e += 8) {
        int2 ea = g_edge[e + eg];
        int2 eb = g_edge[e + 4 + eg];
        uint4 va = ((const uint4*)(src + (size_t)ea.x * 64))[cg];
        uint4 vb = ((const uint4*)(src + (size_t)eb.x * 64))[cg];
        float fa[8], fb[8];
        h8_to_f8(va, fa);
        h8_to_f8(vb, fb);
        float wa = __int_as_float(ea.y), wb = __int_as_float(eb.y);
        #pragma unroll
        for (int j = 0; j < 8; ++j) {
            acc[j] = fmaf(wa, fa[j], acc[j]);
            acc[j] = fmaf(wb, fb[j], acc[j]);
        }
    }
    for (; e < end; e += 4) {
        int2 ea = (e + eg < end) ? g_edge[e + eg] : make_int2(0, 0);
        uint4 va = ((const uint4*)(src + (size_t)ea.x * 64))[cg];
        float fa[8];
        h8_to_f8(va, fa);
        float wa = __int_as_float(ea.y);
        #pragma unroll
        for (int j = 0; j < 8; ++j) acc[j] = fmaf(wa, fa[j], acc[j]);
    }
    #pragma unroll
    for (int j = 0; j < 8; ++j) {
        acc[j] += __shfl_xor_sync(0xffffffffu, acc[j], 8);
        acc[j] += __shfl_xor_sync(0xffffffffu, acc[j], 16);
    }

    if (!DEEP) {
        if (lane < 8) {
            const float4* rp = (const float4*)(root + (size_t)n * 64);
            float4 r0 = rp[cg * 2], r1 = rp[cg * 2 + 1];
            float y[8];
            y[0] = fmaxf(acc[0] + r0.x, 0.f); y[1] = fmaxf(acc[1] + r0.y, 0.f);
            y[2] = fmaxf(acc[2] + r0.z, 0.f); y[3] = fmaxf(acc[3] + r0.w, 0.f);
            y[4] = fmaxf(acc[4] + r1.x, 0.f); y[5] = fmaxf(acc[5] + r1.y, 0.f);
            y[6] = fmaxf(acc[6] + r1.z, 0.f); y[7] = fmaxf(acc[7] + r1.w, 0.f);
            *(uint4*)&outB[(size_t)n * 64 + cg * 8] = f8_to_h8(y);
        }
        return;
    }

    if (lane < 8) {
        #pragma unroll
        for (int j = 0; j < 8; ++j) smr[wwarp][cg * 8 + j] = acc[j];
    }
    __syncwarp();
    float a0 = smr[wwarp][lane];
    float a1 = smr[wwarp][lane + 32];

    float z0 = 0.f, z1 = 0.f;
    #pragma unroll
    for (int l = 0; l < 32; ++l) {
        float b0  = __shfl_sync(0xffffffffu, a0, l);
        float b1v = __shfl_sync(0xffffffffu, a1, l);
        z0 = fmaf(b0,  wd[0][l][lane], z0);
        z1 = fmaf(b1v, wd[1][l][lane], z1);
    }

    const float* rp = root + (size_t)n * 64;
    float y0 = fmaxf(z0 + rp[lane],      0.f);
    float y1 = fmaxf(z1 + rp[lane + 32], 0.f);
    outH[(size_t)n * 128 + lane] = __float2half_rn(0.5f * (y0 + y1));
}

// ---------------- prop32h: width-32 fp16 gather, warp per node ----------------
template <int SOFF, int DOFF, bool WITH_S>
__global__ void prop32h_kernel(__half* __restrict__ buf) {
    const int gwarp = (blockIdx.x * blockDim.x + threadIdx.x) >> 5;
    const int lane  = threadIdx.x & 31;
    if (gwarp >= NN) return;
    const int n   = gwarp;
    const int beg = g_off[n];
    const int end = g_off[n + 1];
    const int eg = lane >> 2, cg = lane & 3;
    const __half* src = buf + SOFF;

    float acc[8] = {};
    float sw = 0.f;
    int e = beg;
    for (; e + 16 <= end; e += 16) {
        int2 ea = g_edge[e + eg];
        int2 eb = g_edge[e + 8 + eg];
        uint4 va = ((const uint4*)(src + (size_t)ea.x * 128))[cg];
        uint4 vb = ((const uint4*)(src + (size_t)eb.x * 128))[cg];
        float fa[8], fb[8];
        h8_to_f8(va, fa);
        h8_to_f8(vb, fb);
        float wa = __int_as_float(ea.y), wb = __int_as_float(eb.y);
        #pragma unroll
        for (int j = 0; j < 8; ++j) {
            acc[j] = fmaf(wa, fa[j], acc[j]);
            acc[j] = fmaf(wb, fb[j], acc[j]);
        }
        if (WITH_S) sw += wa + wb;
    }
    for (; e < end; e += 8) {
        int2 ea = (e + eg < end) ? g_edge[e + eg] : make_int2(0, 0);
        uint4 va = ((const uint4*)(src + (size_t)ea.x * 128))[cg];
        float fa[8];
        h8_to_f8(va, fa);
        float wa = __int_as_float(ea.y);
        #pragma unroll
        for (int j = 0; j < 8; ++j) acc[j] = fmaf(wa, fa[j], acc[j]);
        if (WITH_S) sw += wa;
    }
    #pragma unroll
    for (int j = 0; j < 8; ++j) {
        acc[j] += __shfl_xor_sync(0xffffffffu, acc[j], 4);
        acc[j] += __shfl_xor_sync(0xffffffffu, acc[j], 8);
        acc[j] += __shfl_xor_sync(0xffffffffu, acc[j], 16);
    }
    if (WITH_S) {
        sw += __shfl_xor_sync(0xffffffffu, sw, 4);
        sw += __shfl_xor_sync(0xffffffffu, sw, 8);
        sw += __shfl_xor_sync(0xffffffffu, sw, 16);
    }
    if (lane < 4)
        *(uint4*)&buf[(size_t)n * 128 + DOFF + cg * 8] = f8_to_h8(acc);
    if (WITH_S && lane == 0) g_s[n] = sw;
}

// ---------------- gemm96 (fp16 X) + fused log_softmax ----------------
__global__ void __launch_bounds__(256)
gemm96lsm_kernel(const __half* __restrict__ X,      // H16, ld 128 (cols 0..95)
                 const float* __restrict__ W,       // 96 x 40
                 float* __restrict__ out, int nrows) {
    __shared__ float xs[16][132];
    __shared__ float ws[16][40];
    __shared__ float sbG[40], sbR[40];

    const int tid = threadIdx.x;
    const int tx  = tid & 7;
    const int ty  = tid >> 3;
    const int n0  = blockIdx.x * 128;

    if (tid < 40) { sbG[tid] = g_bG[tid]; sbR[tid] = g_bR[tid]; }

    float acc[4][5] = {};

    for (int f0 = 0; f0 < 96; f0 += 16) {
        {
            int m = tid >> 1, q = tid & 1;
            uint4 v = make_uint4(0, 0, 0, 0);
            if (n0 + m < nrows)
                v = *(const uint4*)&X[(size_t)(n0 + m) * 128 + f0 + q * 8];
            float fv[8];
            h8_to_f8(v, fv);
            #pragma unroll
            for (int j = 0; j < 8; ++j) xs[q * 8 + j][m] = fv[j];
        }
        #pragma unroll
        for (int l = 0; l < 3; ++l) {
            int idx = tid + l * 256;
            if (idx < 640) {
                int f = idx / 40, j = idx - f * 40;
                ws[f][j] = W[(size_t)(f0 + f) * 40 + j];
            }
        }
        __syncthreads();
        #pragma unroll
        for (int f = 0; f < 16; ++f) {
            float w[5];
            #pragma unroll
            for (int c = 0; c < 5; ++c) w[c] = ws[f][tx * 5 + c];
            #pragma unroll
            for (int r = 0; r < 4; ++r) {
                float xv = xs[f][ty * 4 + r];
                #pragma unroll
                for (int c = 0; c < 5; ++c) acc[r][c] = fmaf(xv, w[c], acc[r][c]);
            }
        }
        __syncthreads();
    }

    #pragma unroll
    for (int r = 0; r < 4; ++r) {
        int n = n0 + ty * 4 + r;
        float sv = (n < nrows) ? g_s[n] : 0.f;
        float y[5];
        #pragma unroll
        for (int c = 0; c < 5; ++c) {
            int j = tx * 5 + c;
            y[c] = acc[r][c] + sv * sbG[j] + sbR[j];
        }
        float m = y[0];
        #pragma unroll
        for (int c = 1; c < 5; ++c) m = fmaxf(m, y[c]);
        #pragma unroll
        for (int o = 1; o < 8; o <<= 1) m = fmaxf(m, __shfl_xor_sync(0xffffffffu, m, o));
        float s = 0.f;
        #pragma unroll
        for (int c = 0; c < 5; ++c) s += expf(y[c] - m);
        #pragma unroll
        for (int o = 1; o < 8; o <<= 1) s += __shfl_xor_sync(0xffffffffu, s, o);
        float lse = m + logf(s);
        if (n < nrows) {
            #pragma unroll
            for (int c = 0; c < 5; ++c)
                out[(size_t)n * 40 + tx * 5 + c] = y[c] - lse;
        }
    }
}

// ---------------- launch ----------------
extern "C" void kernel_launch(void* const* d_in, const int* in_sizes, int n_in,
                              void* d_out, int out_size) {
    const float* x    = (const float*)d_in[0];
    const int*   eidx = (const int*)  d_in[1];
    const float* w1i  = (const float*)d_in[2];
    const float* w1d  = (const float*)d_in[3];
    const float* w1r  = (const float*)d_in[4];
    const float* b1   = (const float*)d_in[5];
    const float* w2i  = (const float*)d_in[6];
    const float* w2d  = (const float*)d_in[7];
    const float* w2r  = (const float*)d_in[8];
    const float* b2   = (const float*)d_in[9];
    float* outp = (float*)d_out;

    const int* row = eidx;
    const int* col = eidx + EE;

    __half *A16, *B16, *H16;
    float *Ar, *Wp1, *W3;
    cudaGetSymbolAddress((void**)&A16, g_A16);
    cudaGetSymbolAddress((void**)&Ar,  g_Ar);
    cudaGetSymbolAddress((void**)&B16, g_B16);
    cudaGetSymbolAddress((void**)&H16, g_H16);
    cudaGetSymbolAddress((void**)&Wp1, g_Wp1);
    cudaGetSymbolAddress((void**)&W3,  g_W3);

    static cudaStream_t s2 = nullptr;
    static cudaEvent_t  evFork = nullptr, evJoin = nullptr;
    if (s2 == nullptr) {
        cudaStreamCreateWithFlags(&s2, cudaStreamNonBlocking);
        cudaEventCreateWithFlags(&evFork, cudaEventDisableTiming);
        cudaEventCreateWithFlags(&evJoin, cudaEventDisableTiming);
    }

    const int TB = 256;
    const int nblkE4 = (EE / 4 + TB - 1) / TB;         // 782
    const int nblkW  = (NN * 32 + TB - 1) / TB;        // 6250 (warp per node)
    const int gR = (NN + 127) / 128;                   // 391 row tiles

    // fork immediately: side stream does weight folding + gemm128
    cudaEventRecord(evFork, 0);
    cudaStreamWaitEvent(s2, evFork, 0);
    initW_kernel<<<(16384 + 96 * 40 + 80 + TB - 1) / TB, TB, 0, s2>>>(w1i, w1r, w2i, w2d, w2r, b2);
    gemm128_kernel<<<gR, TB, 0, s2>>>(x, Wp1, b1, A16, Ar, NN);
    cudaEventRecord(evJoin, s2);

    // main stream: graph prep (rank-fused CSR build, no fill atomics)
    initD_kernel<<<NBLK_SCAN, TB>>>();
    rank_kernel<<<nblkE4, TB>>>(col);
    scanA_kernel<<<NBLK_SCAN, 256>>>();
    scanC_kernel<<<NBLK_SCAN, 256>>>();
    fill2_kernel<<<nblkE4, TB>>>(row, col);

    cudaStreamWaitEvent(0, evJoin, 0);

    // ---- conv1 (fp16 gathers, fp32 math) ----
    prop64h_kernel<false><<<nblkW, TB>>>(A16, Ar, nullptr, B16, nullptr);
    prop64h_kernel<true ><<<nblkW, TB>>>(B16, Ar, w1d, nullptr, H16);  // H -> cols 0..31

    // ---- conv2 (fully folded, fp16 features) ----
    prop32h_kernel<0, 32, true ><<<nblkW, TB>>>(H16);        // PH  = A(H),  + s[n]
    prop32h_kernel<32, 64, false><<<nblkW, TB>>>(H16);       // PPH = A(PH)
    gemm96lsm_kernel<<<gR, TB>>>(H16, W3, outp, NN);
}